// round 10
// baseline (speedup 1.0000x reference)
#include <cuda_runtime.h>

// SoftmaxProbs: mean = (1/B) * sum_{b,c} l[b,c] * (lse_b - x[b,c])
// 2M rows x 18 classes fp32, HBM-bound (288 MB).
// WARP-DECOUPLED pipelines: each warp owns a 32-row slice of every chunk,
// its own cp.async double buffer and rowlse -> only __syncwarp, no block
// barriers in the main loop. Labels streamed with batched LDG.128 (MLP 4-5).

#define NC 18
#define BLK 256
#define NWARP (BLK / 32)
#define RPW 32                        // rows per warp per chunk
#define WF  (RPW * NC)                // 576 floats per warp-slice
#define WV4 (WF / 4)                  // 144 float4 per warp-slice
#define MAX_GRID 2048

__device__ double       g_partials[MAX_GRID];
__device__ unsigned int g_count = 0;

__device__ __forceinline__ void cpa16(unsigned int saddr, const float4* g) {
    asm volatile("cp.async.cg.shared.global [%0], [%1], 16;" :: "r"(saddr), "l"(g));
}
__device__ __forceinline__ void cpa_commit() {
    asm volatile("cp.async.commit_group;");
}

__global__ __launch_bounds__(BLK, 4)
void ce_main_kernel(const float* __restrict__ x,
                    const float* __restrict__ lab,
                    float* __restrict__ out,
                    int B, int nchunks)
{
    __shared__ float  sx[2][NWARP][WF];     // 36864 B
    __shared__ float  rowlse[NWARP][RPW];   // 1024 B
    __shared__ double sred[NWARP];
    __shared__ int    s_last;

    const int tid  = threadIdx.x;
    const int w    = tid >> 5;
    const int lane = tid & 31;

    // Stage this warp's 32-row slice of chunk c into sx[s][w].
    auto stage_w = [&](int c, int s) {
        const long long r0 = (long long)c * BLK + (long long)w * RPW;
        long long rem = (long long)B - r0;
        if (rem <= 0) return;
        const int wr = rem < RPW ? (int)rem : RPW;
        const float* xb = x + r0 * NC;
        if (wr == RPW) {
            const float4* xb4 = (const float4*)xb;   // base 16B-aligned (2304B slices)
            const unsigned sxa = (unsigned)__cvta_generic_to_shared(&sx[s][w][0]);
            #pragma unroll
            for (int j = 0; j < 4; j++)              // 128 of 144
                cpa16(sxa + (lane + j * 32) * 16, xb4 + lane + j * 32);
            if (lane < WV4 - 128)                    // last 16: lanes 0..15
                cpa16(sxa + (lane + 128) * 16, xb4 + lane + 128);
        } else {                                     // rare tail: scalar STS
            const int nf = wr * NC;
            for (int i = lane; i < nf; i += 32)
                sx[s][w][i] = xb[i];
        }
    };

    const int c0 = blockIdx.x;
    double acc = 0.0;

    stage_w(c0, 0);
    cpa_commit();

    int stg = 0;
    for (int c = c0; c < nchunks; c += gridDim.x, stg ^= 1) {
        const int nxt = c + gridDim.x;
        if (nxt < nchunks) stage_w(nxt, stg ^ 1);
        cpa_commit();
        asm volatile("cp.async.wait_group 1;");      // this warp's slice of c resident
        __syncwarp();

        const long long r0 = (long long)c * BLK + (long long)w * RPW;
        long long rem = (long long)B - r0;
        const int wr = rem <= 0 ? 0 : (rem < RPW ? (int)rem : RPW);

        // ── Phase 1: per-row LSE (72 B stride LDS: conflict-free) ──
        if (lane < wr) {
            const float* rx = &sx[stg][w][lane * NC];
            float xr[NC];
            #pragma unroll
            for (int k = 0; k < NC; k++) xr[k] = rx[k];
            float m = xr[0];
            #pragma unroll
            for (int k = 1; k < NC; k++) m = fmaxf(m, xr[k]);
            float s = 0.f;
            #pragma unroll
            for (int k = 0; k < NC; k++) s += __expf(xr[k] - m);
            rowlse[w][lane] = m + __logf(s);
        }
        __syncwarp();

        // ── Phase 2: labels via batched LDG.128, elementwise l*(lse-x) ──
        float facc = 0.f;
        const float* lb = lab + r0 * NC;

        auto consume = [&](float4 lv, int i) {
            const float4 xv = ((const float4*)&sx[stg][w][0])[i];
            const int e = i << 2;
            facc += lv.x * (rowlse[w][(e    ) / NC] - xv.x);
            facc += lv.y * (rowlse[w][(e + 1) / NC] - xv.y);
            facc += lv.z * (rowlse[w][(e + 2) / NC] - xv.z);
            facc += lv.w * (rowlse[w][(e + 3) / NC] - xv.w);
        };

        if (wr == RPW) {
            const float4* lb4 = (const float4*)lb;
            float4 L0 = lb4[lane       ];
            float4 L1 = lb4[lane +  32 ];
            float4 L2 = lb4[lane +  64 ];
            float4 L3 = lb4[lane +  96 ];
            float4 L4;
            const bool has5 = lane < (WV4 - 128);    // lanes 0..15
            if (has5) L4 = lb4[lane + 128];

            consume(L0, lane      );
            consume(L1, lane +  32);
            consume(L2, lane +  64);
            consume(L3, lane +  96);
            if (has5) consume(L4, lane + 128);
        } else if (wr > 0) {                         // rare tail
            const int nf = wr * NC;
            for (int i = lane; i < nf; i += 32)
                facc += lb[i] * (rowlse[w][i / NC] - sx[stg][w][i]);
        }
        acc += (double)facc;                         // one DADD per chunk
        __syncwarp();                                // slice reusable for restage
    }
    asm volatile("cp.async.wait_group 0;");

    // ── per-warp then per-block deterministic reduction ──
    #pragma unroll
    for (int o = 16; o > 0; o >>= 1)
        acc += __shfl_down_sync(0xffffffffu, acc, o);
    if (lane == 0) sred[w] = acc;
    __syncthreads();

    if (tid == 0) {
        double v = 0.0;
        #pragma unroll
        for (int i = 0; i < NWARP; i++) v += sred[i];
        g_partials[blockIdx.x] = v;
        __threadfence();
        unsigned prev = atomicAdd(&g_count, 1u);
        s_last = (prev == gridDim.x - 1u) ? 1 : 0;
    }
    __syncthreads();

    // ── fused finalize: last block sums all partials ──
    if (s_last) {
        double v = 0.0;
        for (int i = tid; i < (int)gridDim.x; i += BLK)
            v += g_partials[i];
        #pragma unroll
        for (int o = 16; o > 0; o >>= 1)
            v += __shfl_down_sync(0xffffffffu, v, o);
        if (lane == 0) sred[w] = v;
        __syncthreads();
        if (tid == 0) {
            double t = 0.0;
            #pragma unroll
            for (int i = 0; i < NWARP; i++) t += sred[i];
            out[0] = (float)(t / (double)B);
            g_count = 0;                             // reset for next graph replay
        }
    }
}

extern "C" void kernel_launch(void* const* d_in, const int* in_sizes, int n_in,
                              void* d_out, int out_size)
{
    const float* x   = (const float*)d_in[0];   // output       [B, 18]
    const float* lab = (const float*)d_in[1];   // labels_soft  [B, 18]
    const int B = in_sizes[0] / NC;
    const int nchunks = (B + BLK - 1) / BLK;

    int grid = 148 * 4;                 // 4 blocks/SM (37 KB smem each)
    if (grid > nchunks) grid = nchunks;
    if (grid > MAX_GRID) grid = MAX_GRID;

    ce_main_kernel<<<grid, BLK>>>(x, lab, (float*)d_out, B, nchunks);
}